// round 8
// baseline (speedup 1.0000x reference)
#include <cuda_runtime.h>
#include <cuda_fp8.h>
#include <stdint.h>

// ---------------- problem constants ----------------
#define DIM        512
#define NPAIR      8192
#define TILE_M     64
#define TILE_N     256
#define NIT        128            // 8192 / 64 i-tiles
#define JITERS     16             // j-iterations per CTA (half range / 256)
#define NKC        4              // K chunks of 128 e4m3 (128 B per row)
#define PBLK       8192           // P chunk: 64 rows x 128 B
#define BBLK       32768          // B chunk: 256 rows x 128 B
#define TOTAL_CHUNKS (JITERS * NKC)   // 64
#define QSCALE     16.0f          // fp8 pre-scale (avoids denormal tail)
#define INV_S2     (1.0f / 256.0f)    // 1/16^2, exact power of two

// ---------------- smem layout (offsets from 1024-aligned base) ----------------
#define SM_P       0
#define SM_AB      (SM_P + NKC * PBLK)               // 32768
#define SM_RED     (SM_AB + 2 * BBLK)                // 98304 (double buffer)
#define SM_END     (SM_RED + 64 * 8 * 4)             // 100352
#define SM_DYN     (SM_END + 1024)                   // 101376 -> 2 CTAs/SM

// ---------------- device scratch (static: allowed) ----------------
__device__ uint8_t g_P[(size_t)NPAIR * DIM];   // e4m3 positive rows (x16 scale)
__device__ uint8_t g_A[(size_t)NPAIR * DIM];   // e4m3 anchor rows (x16 scale)
__device__ float g_partial[2 * NPAIR];         // per-half row exp-sums
__device__ float g_diag[NPAIR];                // fp32 cos_ii (exact)
__device__ float g_blk[32];                    // finalize stage-1 partials

// ---------------- PTX helpers (base-ISA only: no tcgen05 on compute_103) ----------------
static __device__ __forceinline__ uint32_t smem_u32(const void* p) {
    uint32_t a;
    asm("{ .reg .u64 t; cvta.to.shared.u64 t, %1; cvt.u32.u64 %0, t; }"
        : "=r"(a) : "l"(p));
    return a;
}

#define CPA16(dst, src) \
    asm volatile("cp.async.cg.shared.global [%0], [%1], 16;" :: "r"(dst), "l"(src))
#define CPA_COMMIT() asm volatile("cp.async.commit_group;" ::: "memory")
#define CPA_WAIT1()  asm volatile("cp.async.wait_group 1;" ::: "memory")

#define LDSM4(r0, r1, r2, r3, addr) \
    asm volatile("ldmatrix.sync.aligned.m8n8.x4.shared.b16 {%0,%1,%2,%3}, [%4];" \
                 : "=r"(r0), "=r"(r1), "=r"(r2), "=r"(r3) : "r"(addr))

// e4m3 x e4m3 -> fp32, K=32 per instruction (fragment layout proven in R4/R7).
static __device__ __forceinline__ void mma_e4m3(float* d, const uint32_t* a,
                                                const uint32_t* b) {
    asm volatile(
        "mma.sync.aligned.m16n8k32.row.col.f32.e4m3.e4m3.f32 "
        "{%0,%1,%2,%3}, {%4,%5,%6,%7}, {%8,%9}, {%0,%1,%2,%3};"
        : "+f"(d[0]), "+f"(d[1]), "+f"(d[2]), "+f"(d[3])
        : "r"(a[0]), "r"(a[1]), "r"(a[2]), "r"(a[3]), "r"(b[0]), "r"(b[1]));
}

static __device__ __forceinline__ uint32_t pack_fp8x4(float4 v, float s) {
    float4 t = make_float4(v.x * s, v.y * s, v.z * s, v.w * s);
    __nv_fp8x4_e4m3 q(t);
    return *(uint32_t*)&q;
}

// ---------------- kernel 1: per-pair normalize + fp8 write + exact fp32 diag ----------------
__global__ void __launch_bounds__(256) prep_kernel(const float* __restrict__ x) {
    int pair = blockIdx.x * 8 + (threadIdx.x >> 5);
    int lid = threadIdx.x & 31;
    const float4* ar = (const float4*)(x + (size_t)(2 * pair) * DIM);      // anchor
    const float4* pr = (const float4*)(x + (size_t)(2 * pair + 1) * DIM);  // positive
    float4 va[4], vp[4];
    float ssa = 0.f, ssp = 0.f, dp = 0.f;
#pragma unroll
    for (int i = 0; i < 4; i++) {
        va[i] = ar[lid + i * 32];
        vp[i] = pr[lid + i * 32];
        ssa += va[i].x * va[i].x + va[i].y * va[i].y + va[i].z * va[i].z + va[i].w * va[i].w;
        ssp += vp[i].x * vp[i].x + vp[i].y * vp[i].y + vp[i].z * vp[i].z + vp[i].w * vp[i].w;
        dp  += va[i].x * vp[i].x + va[i].y * vp[i].y + va[i].z * vp[i].z + va[i].w * vp[i].w;
    }
#pragma unroll
    for (int o = 16; o; o >>= 1) {
        ssa += __shfl_xor_sync(0xffffffffu, ssa, o);
        ssp += __shfl_xor_sync(0xffffffffu, ssp, o);
        dp  += __shfl_xor_sync(0xffffffffu, dp, o);
    }
    float inva = rsqrtf(ssa);   // norms ~sqrt(512): EPS clamp never binds
    float invp = rsqrtf(ssp);
    if (lid == 0) g_diag[pair] = dp * inva * invp;   // exact fp32 diagonal

    uint32_t* da = (uint32_t*)(g_A + (size_t)pair * DIM);
    uint32_t* dq = (uint32_t*)(g_P + (size_t)pair * DIM);
    float sa = inva * QSCALE, sp = invp * QSCALE;
#pragma unroll
    for (int i = 0; i < 4; i++) {
        da[lid + i * 32] = pack_fp8x4(va[i], sa);
        dq[lid + i * 32] = pack_fp8x4(vp[i], sp);
    }
}

// ---------------- kernel 2: fused cos-GEMM (e4m3 mma, 2 CTAs/SM) + exp row-sums ----------------
__global__ void __launch_bounds__(256, 2) angle_main(const float* __restrict__ wp) {
    extern __shared__ char smem_raw[];
    uint32_t sb_raw = smem_u32(smem_raw);
    uint32_t pad = ((sb_raw + 1023u) & ~1023u) - sb_raw;
    char* smem = smem_raw + pad;
    uint32_t sbase = sb_raw + pad;

    const int tid = threadIdx.x, wid = tid >> 5, lid = tid & 31;
    const int wn = wid;                            // 1 x 8 warp grid, 64x32 tiles
    const int it = blockIdx.x >> 1;                // i-tile (64 positive rows)
    const int half = blockIdx.x & 1;               // anchor half
    const float wexp = (*wp) * INV_S2;             // acc -> w*cos

    // ldmatrix lane geometry (xor-swizzled 16B chunks within 128B rows)
    const int a_row0 = (lid & 7) + ((lid >> 3) & 1) * 8;            // + mf*16
    const int a_k = lid >> 4;
    const int a_sw = a_row0 & 7;
    const int b_row0 = wn * 32 + (lid & 7) + ((lid >> 4) & 1) * 8;  // + p*16
    const int b_k = (lid >> 3) & 1;
    const int b_sw = b_row0 & 7;

    // ---- resident P tile: 4 swizzled chunks of [64 rows x 128 B] ----
    {
        const char* src = (const char*)(g_P + (size_t)it * TILE_M * DIM);
        for (int i = tid; i < NKC * 512; i += 256) {
            int blk = i >> 9, v = i & 511;
            int row = v >> 3, c = v & 7;
            CPA16(sbase + SM_P + blk * PBLK + row * 128 + ((c ^ (row & 7)) << 4),
                  src + (size_t)row * DIM + blk * 128 + c * 16);
        }
        CPA_COMMIT();
    }
    // ---- issue anchor chunk 0 (256 rows x 128 B) ----
    {
        const char* src = (const char*)(g_A + (size_t)(half * JITERS) * TILE_N * DIM);
        for (int u = tid; u < 2048; u += 256) {
            int row = u >> 3, cc = u & 7;
            CPA16(sbase + SM_AB + row * 128 + ((cc ^ (row & 7)) << 4),
                  src + (size_t)row * DIM + cc * 16);
        }
        CPA_COMMIT();
    }

    float acc[4][4][4];                            // 64 fp32 regs
#pragma unroll
    for (int mf = 0; mf < 4; mf++)
#pragma unroll
        for (int nf = 0; nf < 4; nf++)
#pragma unroll
            for (int k = 0; k < 4; k++) acc[mf][nf][k] = 0.f;
    float rs[8];
#pragma unroll
    for (int r = 0; r < 8; r++) rs[r] = 0.f;

#pragma unroll 1
    for (int c = 0; c < TOTAL_CHUNKS; ++c) {
        // issue chunk c+1 into the other buffer
        {
            int cn = c + 1;
            if (cn < TOTAL_CHUNKS) {
                int jt = half * JITERS + (cn >> 2), kc = cn & 3;
                const char* src = (const char*)(g_A + (size_t)jt * TILE_N * DIM) + kc * 128;
                uint32_t dst = sbase + SM_AB + (cn & 1) * BBLK;
                for (int u = tid; u < 2048; u += 256) {
                    int row = u >> 3, cc = u & 7;
                    CPA16(dst + row * 128 + ((cc ^ (row & 7)) << 4),
                          src + (size_t)row * DIM + cc * 16);
                }
            }
            CPA_COMMIT();
        }
        CPA_WAIT1();        // chunk c (and P on first iter) resident
        __syncthreads();

        // ---- compute chunk c: 128 k-elems = 4 mma k-steps of K=32 ----
        const uint32_t pb = sbase + SM_P + (c & 3) * PBLK;
        const uint32_t bb = sbase + SM_AB + (c & 1) * BBLK;
#pragma unroll
        for (int ks = 0; ks < 4; ++ks) {
            uint32_t a[4][4];
#pragma unroll
            for (int mf = 0; mf < 4; ++mf) {
                uint32_t addr = pb + (uint32_t)(a_row0 + mf * 16) * 128 +
                                (uint32_t)(((2 * ks + a_k) ^ a_sw) << 4);
                LDSM4(a[mf][0], a[mf][1], a[mf][2], a[mf][3], addr);
            }
            uint32_t b[4][2];
#pragma unroll
            for (int p = 0; p < 2; ++p) {
                uint32_t addr = bb + (uint32_t)(b_row0 + p * 16) * 128 +
                                (uint32_t)(((2 * ks + b_k) ^ b_sw) << 4);
                uint32_t r0, r1, r2, r3;
                LDSM4(r0, r1, r2, r3, addr);
                b[2 * p][0] = r0; b[2 * p][1] = r1;
                b[2 * p + 1][0] = r2; b[2 * p + 1][1] = r3;
            }
#pragma unroll
            for (int mf = 0; mf < 4; ++mf)
#pragma unroll
                for (int nf = 0; nf < 4; ++nf)
                    mma_e4m3(acc[mf][nf], a[mf], b[nf]);
        }

        // ---- per-j-iter epilogue: exp-accumulate, reset accumulators ----
        if ((c & 3) == 3) {
#pragma unroll
            for (int mf = 0; mf < 4; ++mf)
#pragma unroll
                for (int nf = 0; nf < 4; ++nf) {
                    rs[mf * 2 + 0] += __expf(wexp * acc[mf][nf][0]) +
                                      __expf(wexp * acc[mf][nf][1]);
                    rs[mf * 2 + 1] += __expf(wexp * acc[mf][nf][2]) +
                                      __expf(wexp * acc[mf][nf][3]);
#pragma unroll
                    for (int k = 0; k < 4; k++) acc[mf][nf][k] = 0.f;
                }
        }
        __syncthreads();   // all warps done with buf (c&1) before iter c+1 overwrites it
    }

    // ---- deterministic CTA reduction: lanes -> warps(wn) -> rows ----
#pragma unroll
    for (int r = 0; r < 8; ++r) {
        rs[r] += __shfl_xor_sync(0xffffffffu, rs[r], 1);
        rs[r] += __shfl_xor_sync(0xffffffffu, rs[r], 2);
    }
    float* red = (float*)(smem + SM_RED);
    __syncthreads();
    if ((lid & 3) == 0) {
        int g = lid >> 2;
#pragma unroll
        for (int mf = 0; mf < 4; ++mf) {
            int rl0 = mf * 16 + g;
            red[(rl0) * 8 + wn] = rs[mf * 2 + 0];
            red[(rl0 + 8) * 8 + wn] = rs[mf * 2 + 1];
        }
    }
    __syncthreads();
    if (tid < 64) {
        float s = 0.f;
#pragma unroll
        for (int q = 0; q < 8; ++q) s += red[tid * 8 + q];
        g_partial[half * NPAIR + it * TILE_M + tid] = s;
    }
}

// ---------------- kernel 3: per-row log + block partial (32 CTAs) ----------------
__global__ void __launch_bounds__(256) lse_kernel(const float* __restrict__ wp) {
    __shared__ float red[256];
    int tid = threadIdx.x;
    int i = blockIdx.x * 256 + tid;
    float w = *wp;
    float es = g_partial[i] + g_partial[NPAIR + i];
    red[tid] = logf(es) - w * g_diag[i];
    __syncthreads();
    for (int o = 128; o; o >>= 1) {
        if (tid < o) red[tid] += red[tid + o];
        __syncthreads();
    }
    if (tid == 0) g_blk[blockIdx.x] = red[0];
}

// ---------------- kernel 4: final scalar ----------------
__global__ void finalize_kernel(float* __restrict__ out) {
    int lid = threadIdx.x;
    float s = g_blk[lid];
#pragma unroll
    for (int o = 16; o; o >>= 1) s += __shfl_xor_sync(0xffffffffu, s, o);
    if (lid == 0) out[0] = s / (float)NPAIR;
}

// ---------------- launch ----------------
extern "C" void kernel_launch(void* const* d_in, const int* in_sizes, int n_in,
                              void* d_out, int out_size) {
    const float* x = (const float*)d_in[0];
    const float* wp = (const float*)d_in[1];
    // b cancels analytically: lse_i - logit_ii is independent of b.

    cudaFuncSetAttribute(angle_main, cudaFuncAttributeMaxDynamicSharedMemorySize, SM_DYN);

    prep_kernel<<<NPAIR / 8, 256>>>(x);
    angle_main<<<NIT * 2, 256, SM_DYN>>>(wp);
    lse_kernel<<<32, 256>>>(wp);
    finalize_kernel<<<1, 32>>>((float*)d_out);
}

// round 9
// speedup vs baseline: 1.2215x; 1.2215x over previous
#include <cuda_runtime.h>
#include <cuda_bf16.h>
#include <stdint.h>

// ---------------- problem constants ----------------
#define DIM        512
#define NPAIR      8192
#define TILE_M     128
#define TILE_N     256
#define NUNITS     2048           // 64 i-tiles x 32 j-tiles (128x256 each)
#define GRID_MAIN  148            // one CTA per SM, balanced unit ranges
#define NKC        8              // K chunks of 64 bf16 (128 B per row)
#define PBLK       16384          // P chunk: 128 rows x 128 B
#define BBLK       32768          // B chunk: 256 rows x 128 B
#define NBUF       3              // B-chunk ring depth (issue-ahead-2)

// ---------------- smem layout (offsets from 128-aligned base) ----------------
#define SM_P       0
#define SM_AB      (SM_P + NKC * PBLK)               // 131072
#define SM_RED     SM_AB                             // overlay: used only post-drain
#define SM_DYN     (SM_AB + NBUF * BBLK + 128)       // 229504 <= 232448 cap

// ---------------- device scratch (static: allowed; zero-initialized) ----------------
__device__ __nv_bfloat16 g_P[(size_t)NPAIR * DIM];   // normalized positive rows
__device__ __nv_bfloat16 g_A[(size_t)NPAIR * DIM];   // normalized anchor rows
__device__ float g_partial[64 * 32 * 128];           // [i-tile][slot][row], unwritten=0
__device__ float g_diag[NPAIR];                      // fp32 cos_ii (exact)
__device__ float g_blk[32];                          // finalize stage-1 partials

// ---------------- PTX helpers (base-ISA only: no tcgen05 on compute_103) ----------------
static __device__ __forceinline__ uint32_t smem_u32(const void* p) {
    uint32_t a;
    asm("{ .reg .u64 t; cvta.to.shared.u64 t, %1; cvt.u32.u64 %0, t; }"
        : "=r"(a) : "l"(p));
    return a;
}

#define CPA16(dst, src) \
    asm volatile("cp.async.cg.shared.global [%0], [%1], 16;" :: "r"(dst), "l"(src))
#define CPA_COMMIT() asm volatile("cp.async.commit_group;" ::: "memory")
#define CPA_WAIT2()  asm volatile("cp.async.wait_group 2;" ::: "memory")
#define CPA_WAIT0()  asm volatile("cp.async.wait_group 0;" ::: "memory")

#define LDSM4(r0, r1, r2, r3, addr) \
    asm volatile("ldmatrix.sync.aligned.m8n8.x4.shared.b16 {%0,%1,%2,%3}, [%4];" \
                 : "=r"(r0), "=r"(r1), "=r"(r2), "=r"(r3) : "r"(addr))

static __device__ __forceinline__ void mma16816(float* d, const uint32_t* a,
                                                const uint32_t* b) {
    asm volatile(
        "mma.sync.aligned.m16n8k16.row.col.f32.bf16.bf16.f32 "
        "{%0,%1,%2,%3}, {%4,%5,%6,%7}, {%8,%9}, {%0,%1,%2,%3};"
        : "+f"(d[0]), "+f"(d[1]), "+f"(d[2]), "+f"(d[3])
        : "r"(a[0]), "r"(a[1]), "r"(a[2]), "r"(a[3]), "r"(b[0]), "r"(b[1]));
}

// ---------------- kernel 1: per-pair normalize + bf16 write + exact fp32 diag ----------------
__global__ void __launch_bounds__(256) prep_kernel(const float* __restrict__ x) {
    int pair = blockIdx.x * 8 + (threadIdx.x >> 5);
    int lid = threadIdx.x & 31;
    const float4* ar = (const float4*)(x + (size_t)(2 * pair) * DIM);      // anchor
    const float4* pr = (const float4*)(x + (size_t)(2 * pair + 1) * DIM);  // positive
    float4 va[4], vp[4];
    float ssa = 0.f, ssp = 0.f, dp = 0.f;
#pragma unroll
    for (int i = 0; i < 4; i++) {
        va[i] = ar[lid + i * 32];
        vp[i] = pr[lid + i * 32];
        ssa += va[i].x * va[i].x + va[i].y * va[i].y + va[i].z * va[i].z + va[i].w * va[i].w;
        ssp += vp[i].x * vp[i].x + vp[i].y * vp[i].y + vp[i].z * vp[i].z + vp[i].w * vp[i].w;
        dp  += va[i].x * vp[i].x + va[i].y * vp[i].y + va[i].z * vp[i].z + va[i].w * vp[i].w;
    }
#pragma unroll
    for (int o = 16; o; o >>= 1) {
        ssa += __shfl_xor_sync(0xffffffffu, ssa, o);
        ssp += __shfl_xor_sync(0xffffffffu, ssp, o);
        dp  += __shfl_xor_sync(0xffffffffu, dp, o);
    }
    float inva = rsqrtf(ssa);   // norms ~sqrt(512): EPS clamp never binds
    float invp = rsqrtf(ssp);
    if (lid == 0) g_diag[pair] = dp * inva * invp;   // exact fp32 diagonal

    __nv_bfloat16* da = g_A + (size_t)pair * DIM;
    __nv_bfloat16* dq = g_P + (size_t)pair * DIM;
#pragma unroll
    for (int i = 0; i < 4; i++) {
        __nv_bfloat162 l0 = __floats2bfloat162_rn(va[i].x * inva, va[i].y * inva);
        __nv_bfloat162 h0 = __floats2bfloat162_rn(va[i].z * inva, va[i].w * inva);
        uint2 pa; pa.x = *(uint32_t*)&l0; pa.y = *(uint32_t*)&h0;
        *(uint2*)(da + (size_t)(lid + i * 32) * 4) = pa;
        __nv_bfloat162 l1 = __floats2bfloat162_rn(vp[i].x * invp, vp[i].y * invp);
        __nv_bfloat162 h1 = __floats2bfloat162_rn(vp[i].z * invp, vp[i].w * invp);
        uint2 pp; pp.x = *(uint32_t*)&l1; pp.y = *(uint32_t*)&h1;
        *(uint2*)(dq + (size_t)(lid + i * 32) * 4) = pp;
    }
}

// issue one B chunk (256 rows x 128 B, swizzled) via cp.async
static __device__ __forceinline__ void issue_bchunk(uint32_t dst, const char* src,
                                                    int tid) {
    for (int u = tid; u < 2048; u += 256) {
        int row = u >> 3, cc = u & 7;
        CPA16(dst + row * 128 + ((cc ^ (row & 7)) << 4),
              src + (size_t)row * (DIM * 2) + cc * 16);
    }
}

// ---------------- kernel 2: balanced fused cos-GEMM + exp row-sums ----------------
__global__ void __launch_bounds__(256, 1) angle_main(const float* __restrict__ wp) {
    extern __shared__ char smem_raw[];
    uint32_t sb_raw = smem_u32(smem_raw);
    uint32_t pad = ((sb_raw + 127u) & ~127u) - sb_raw;
    char* smem = smem_raw + pad;
    uint32_t sbase = sb_raw + pad;

    const int tid = threadIdx.x, wid = tid >> 5, lid = tid & 31;
    const int wm = wid >> 2, wn = wid & 3;         // 2 x 4 warp grid, 64x64 tiles
    const float w = *wp;

    // balanced contiguous unit range for this CTA
    const int s = (blockIdx.x * NUNITS) / GRID_MAIN;
    const int e = ((blockIdx.x + 1) * NUNITS) / GRID_MAIN;
    const int it0 = s >> 5, it1 = (e - 1) >> 5;

    // ldmatrix lane geometry (xor-swizzled 16B chunks within 128B rows)
    const int a_row0 = wm * 64 + (lid & 7) + ((lid >> 3) & 1) * 8;  // + mf*16
    const int a_k = lid >> 4;
    const int a_sw = a_row0 & 7;
    const int b_row0 = wn * 64 + (lid & 7) + ((lid >> 4) & 1) * 8;  // + p*16
    const int b_k = (lid >> 3) & 1;
    const int b_sw = b_row0 & 7;

    float acc[4][8][4];
#pragma unroll
    for (int mf = 0; mf < 4; mf++)
#pragma unroll
        for (int nf = 0; nf < 8; nf++)
#pragma unroll
            for (int k = 0; k < 4; k++) acc[mf][nf][k] = 0.f;

#pragma unroll 1
    for (int it = it0; it <= it1; ++it) {
        const int u_lo = (s > it * 32) ? s : it * 32;
        const int u_hi = (e < (it + 1) * 32) ? e : (it + 1) * 32;
        const int slot = u_lo - it * 32;
        const int nloc = (u_hi - u_lo) * 8;        // chunks this segment (>= 8)

        float rs[8];
#pragma unroll
        for (int r = 0; r < 8; r++) rs[r] = 0.f;

        // ---- segment prologue: P tile + first B chunk in group 0; +2 more ----
        {
            const char* psrc = (const char*)(g_P + (size_t)it * TILE_M * DIM);
            for (int i = tid; i < NKC * 1024; i += 256) {
                int blk = i >> 10, v = i & 1023;
                int row = v >> 3, c = v & 7;
                CPA16(sbase + SM_P + blk * PBLK + row * 128 + ((c ^ (row & 7)) << 4),
                      psrc + (size_t)row * (DIM * 2) + blk * 128 + c * 16);
            }
            int jt0 = u_lo & 31;
            issue_bchunk(sbase + SM_AB,
                         (const char*)(g_A + (size_t)jt0 * TILE_N * DIM), tid);
            CPA_COMMIT();
#pragma unroll
            for (int cpre = 1; cpre < 3; ++cpre) {   // nloc >= 8, no guard needed
                int u = u_lo + (cpre >> 3), jt = u & 31, kc = cpre & 7;
                issue_bchunk(sbase + SM_AB + (cpre % NBUF) * BBLK,
                             (const char*)(g_A + (size_t)jt * TILE_N * DIM) + kc * 128,
                             tid);
                CPA_COMMIT();
            }
        }

#pragma unroll 1
        for (int cl = 0; cl < nloc; ++cl) {
            CPA_WAIT2();         // pending <= 2 -> chunk cl (and P on cl==0) resident
            __syncthreads();

            // ---- compute chunk cl: 64 k-elems = 4 mma k-steps ----
            const uint32_t pb = sbase + SM_P + (cl & 7) * PBLK;
            const uint32_t bb = sbase + SM_AB + (cl % NBUF) * BBLK;
#pragma unroll
            for (int ks = 0; ks < 4; ++ks) {
                uint32_t a[4][4];
#pragma unroll
                for (int mf = 0; mf < 4; ++mf) {
                    uint32_t addr = pb + (uint32_t)(a_row0 + mf * 16) * 128 +
                                    (uint32_t)(((2 * ks + a_k) ^ a_sw) << 4);
                    LDSM4(a[mf][0], a[mf][1], a[mf][2], a[mf][3], addr);
                }
                uint32_t b[8][2];
#pragma unroll
                for (int p = 0; p < 4; ++p) {
                    uint32_t addr = bb + (uint32_t)(b_row0 + p * 16) * 128 +
                                    (uint32_t)(((2 * ks + b_k) ^ b_sw) << 4);
                    uint32_t r0, r1, r2, r3;
                    LDSM4(r0, r1, r2, r3, addr);
                    b[2 * p][0] = r0; b[2 * p][1] = r1;
                    b[2 * p + 1][0] = r2; b[2 * p + 1][1] = r3;
                }
#pragma unroll
                for (int mf = 0; mf < 4; ++mf)
#pragma unroll
                    for (int nf = 0; nf < 8; ++nf)
                        mma16816(acc[mf][nf], a[mf], b[nf]);
            }

            // ---- per-j-tile epilogue: exp-accumulate, reset accumulators ----
            if ((cl & 7) == 7) {
#pragma unroll
                for (int mf = 0; mf < 4; ++mf)
#pragma unroll
                    for (int nf = 0; nf < 8; ++nf) {
                        rs[mf * 2 + 0] += __expf(w * acc[mf][nf][0]) +
                                          __expf(w * acc[mf][nf][1]);
                        rs[mf * 2 + 1] += __expf(w * acc[mf][nf][2]) +
                                          __expf(w * acc[mf][nf][3]);
#pragma unroll
                        for (int k = 0; k < 4; k++) acc[mf][nf][k] = 0.f;
                    }
            }
            __syncthreads();     // all warps done with buf cl%NBUF before reuse

            // issue chunk cl+3 into buf (cl+3)%NBUF == cl%NBUF (safe post-sync)
            {
                int cn = cl + 3;
                if (cn < nloc) {
                    int u = u_lo + (cn >> 3), jt = u & 31, kc = cn & 7;
                    issue_bchunk(sbase + SM_AB + (cn % NBUF) * BBLK,
                                 (const char*)(g_A + (size_t)jt * TILE_N * DIM) + kc * 128,
                                 tid);
                }
                CPA_COMMIT();    // empty groups keep the count aligned
            }
        }

        // ---- segment drain + flush row-sums to g_partial[it][slot][row] ----
        CPA_WAIT0();
        __syncthreads();         // buffers idle: red overlay at SM_AB is safe
#pragma unroll
        for (int r = 0; r < 8; ++r) {
            rs[r] += __shfl_xor_sync(0xffffffffu, rs[r], 1);
            rs[r] += __shfl_xor_sync(0xffffffffu, rs[r], 2);
        }
        float* red = (float*)(smem + SM_RED);
        if ((lid & 3) == 0) {
            int g = lid >> 2;
#pragma unroll
            for (int mf = 0; mf < 4; ++mf) {
                int rl0 = wm * 64 + mf * 16 + g;
                red[(rl0) * 4 + wn] = rs[mf * 2 + 0];
                red[(rl0 + 8) * 4 + wn] = rs[mf * 2 + 1];
            }
        }
        __syncthreads();
        if (tid < 128) {
            float sm = red[tid * 4 + 0] + red[tid * 4 + 1] +
                       red[tid * 4 + 2] + red[tid * 4 + 3];
            g_partial[(it * 32 + slot) * 128 + tid] = sm;
        }
        __syncthreads();         // red read done before next segment reuses buffers
    }
}

// ---------------- kernel 3: per-row log + block partial (32 CTAs) ----------------
__global__ void __launch_bounds__(256) lse_kernel(const float* __restrict__ wp) {
    __shared__ float red[256];
    int tid = threadIdx.x;
    int i = blockIdx.x * 256 + tid;       // global row
    int itile = i >> 7, rloc = i & 127;
    float w = *wp;
    float es = 0.f;
#pragma unroll
    for (int sl = 0; sl < 32; ++sl)
        es += g_partial[(itile * 32 + sl) * 128 + rloc];   // unwritten slots are 0
    red[tid] = logf(es) - w * g_diag[i];
    __syncthreads();
    for (int o = 128; o; o >>= 1) {
        if (tid < o) red[tid] += red[tid + o];
        __syncthreads();
    }
    if (tid == 0) g_blk[blockIdx.x] = red[0];
}

// ---------------- kernel 4: final scalar ----------------
__global__ void finalize_kernel(float* __restrict__ out) {
    int lid = threadIdx.x;
    float s = g_blk[lid];
#pragma unroll
    for (int o = 16; o; o >>= 1) s += __shfl_xor_sync(0xffffffffu, s, o);
    if (lid == 0) out[0] = s / (float)NPAIR;
}

// ---------------- launch ----------------
extern "C" void kernel_launch(void* const* d_in, const int* in_sizes, int n_in,
                              void* d_out, int out_size) {
    const float* x = (const float*)d_in[0];
    const float* wp = (const float*)d_in[1];
    // b cancels analytically: lse_i - logit_ii is independent of b.

    cudaFuncSetAttribute(angle_main, cudaFuncAttributeMaxDynamicSharedMemorySize, SM_DYN);

    prep_kernel<<<NPAIR / 8, 256>>>(x);
    angle_main<<<GRID_MAIN, 256, SM_DYN>>>(wp);
    lse_kernel<<<32, 256>>>(wp);
    finalize_kernel<<<1, 32>>>((float*)d_out);
}

// round 10
// speedup vs baseline: 1.2946x; 1.0598x over previous
#include <cuda_runtime.h>
#include <cuda_bf16.h>
#include <stdint.h>

// ---------------- problem constants ----------------
#define DIM        512
#define NPAIR      8192
#define TILE_M     128
#define TILE_N     256
#define NUNITS     2048           // 64 i-tiles x 32 j-tiles (128x256 each)
#define GRID_MAIN  148            // one CTA per SM, balanced unit ranges
#define NKC        8              // K chunks of 64 bf16 (128 B per row)
#define PBLK       16384          // P chunk: 128 rows x 128 B
#define BBLK       32768          // B chunk: 256 rows x 128 B
#define NBUF       3              // B-chunk ring depth (issue-ahead-2)

// ---------------- smem layout (offsets from 128-aligned base) ----------------
#define SM_P       0
#define SM_AB      (SM_P + NKC * PBLK)               // 131072
#define SM_RED     SM_AB                             // overlay: used only post-drain
#define SM_DYN     (SM_AB + NBUF * BBLK + 128)       // 229504 <= 232448 cap

// ---------------- device scratch (static: allowed; zero-initialized) ----------------
__device__ __nv_bfloat16 g_P[(size_t)NPAIR * DIM];   // normalized positive rows
__device__ __nv_bfloat16 g_A[(size_t)NPAIR * DIM];   // normalized anchor rows
__device__ float g_partial[64 * 32 * 128];           // [i-tile][slot][row], unwritten=0
__device__ float g_diag[NPAIR];                      // fp32 cos_ii (exact)
__device__ float g_blk[32];                          // lse stage-1 partials
__device__ int   g_ctr;                              // last-block arrival counter

// ---------------- PTX helpers (base-ISA only: no tcgen05 on compute_103) ----------------
static __device__ __forceinline__ uint32_t smem_u32(const void* p) {
    uint32_t a;
    asm("{ .reg .u64 t; cvta.to.shared.u64 t, %1; cvt.u32.u64 %0, t; }"
        : "=r"(a) : "l"(p));
    return a;
}

#define CPA16(dst, src) \
    asm volatile("cp.async.cg.shared.global [%0], [%1], 16;" :: "r"(dst), "l"(src))
#define CPA_COMMIT() asm volatile("cp.async.commit_group;" ::: "memory")
#define CPA_WAIT1()  asm volatile("cp.async.wait_group 1;" ::: "memory")
#define CPA_WAIT0()  asm volatile("cp.async.wait_group 0;" ::: "memory")

#define LDSM4(r0, r1, r2, r3, addr) \
    asm volatile("ldmatrix.sync.aligned.m8n8.x4.shared.b16 {%0,%1,%2,%3}, [%4];" \
                 : "=r"(r0), "=r"(r1), "=r"(r2), "=r"(r3) : "r"(addr))

static __device__ __forceinline__ void mma16816(float* d, const uint32_t* a,
                                                const uint32_t* b) {
    asm volatile(
        "mma.sync.aligned.m16n8k16.row.col.f32.bf16.bf16.f32 "
        "{%0,%1,%2,%3}, {%4,%5,%6,%7}, {%8,%9}, {%0,%1,%2,%3};"
        : "+f"(d[0]), "+f"(d[1]), "+f"(d[2]), "+f"(d[3])
        : "r"(a[0]), "r"(a[1]), "r"(a[2]), "r"(a[3]), "r"(b[0]), "r"(b[1]));
}

static __device__ __forceinline__ float ex2f(float x) {
    float r;
    asm("ex2.approx.ftz.f32 %0, %1;" : "=f"(r) : "f"(x));
    return r;
}

// ---------------- kernel 1: per-pair normalize + bf16 write + exact fp32 diag ----------------
__global__ void __launch_bounds__(256) prep_kernel(const float* __restrict__ x) {
    int pair = blockIdx.x * 8 + (threadIdx.x >> 5);
    int lid = threadIdx.x & 31;
    const float4* ar = (const float4*)(x + (size_t)(2 * pair) * DIM);      // anchor
    const float4* pr = (const float4*)(x + (size_t)(2 * pair + 1) * DIM);  // positive
    float4 va[4], vp[4];
    float ssa = 0.f, ssp = 0.f, dp = 0.f;
#pragma unroll
    for (int i = 0; i < 4; i++) {
        va[i] = ar[lid + i * 32];
        vp[i] = pr[lid + i * 32];
        ssa += va[i].x * va[i].x + va[i].y * va[i].y + va[i].z * va[i].z + va[i].w * va[i].w;
        ssp += vp[i].x * vp[i].x + vp[i].y * vp[i].y + vp[i].z * vp[i].z + vp[i].w * vp[i].w;
        dp  += va[i].x * vp[i].x + va[i].y * vp[i].y + va[i].z * vp[i].z + va[i].w * vp[i].w;
    }
#pragma unroll
    for (int o = 16; o; o >>= 1) {
        ssa += __shfl_xor_sync(0xffffffffu, ssa, o);
        ssp += __shfl_xor_sync(0xffffffffu, ssp, o);
        dp  += __shfl_xor_sync(0xffffffffu, dp, o);
    }
    float inva = rsqrtf(ssa);   // norms ~sqrt(512): EPS clamp never binds
    float invp = rsqrtf(ssp);
    if (lid == 0) g_diag[pair] = dp * inva * invp;   // exact fp32 diagonal

    __nv_bfloat16* da = g_A + (size_t)pair * DIM;
    __nv_bfloat16* dq = g_P + (size_t)pair * DIM;
#pragma unroll
    for (int i = 0; i < 4; i++) {
        __nv_bfloat162 l0 = __floats2bfloat162_rn(va[i].x * inva, va[i].y * inva);
        __nv_bfloat162 h0 = __floats2bfloat162_rn(va[i].z * inva, va[i].w * inva);
        uint2 pa; pa.x = *(uint32_t*)&l0; pa.y = *(uint32_t*)&h0;
        *(uint2*)(da + (size_t)(lid + i * 32) * 4) = pa;
        __nv_bfloat162 l1 = __floats2bfloat162_rn(vp[i].x * invp, vp[i].y * invp);
        __nv_bfloat162 h1 = __floats2bfloat162_rn(vp[i].z * invp, vp[i].w * invp);
        uint2 pp; pp.x = *(uint32_t*)&l1; pp.y = *(uint32_t*)&h1;
        *(uint2*)(dq + (size_t)(lid + i * 32) * 4) = pp;
    }
}

// issue one B chunk (256 rows x 128 B, swizzled) via cp.async
static __device__ __forceinline__ void issue_bchunk(uint32_t dst, const char* src,
                                                    int tid) {
    for (int u = tid; u < 2048; u += 256) {
        int row = u >> 3, cc = u & 7;
        CPA16(dst + row * 128 + ((cc ^ (row & 7)) << 4),
              src + (size_t)row * (DIM * 2) + cc * 16);
    }
}

// ---------------- kernel 2: balanced fused cos-GEMM + exp row-sums ----------------
__global__ void __launch_bounds__(256, 1) angle_main(const float* __restrict__ wp) {
    extern __shared__ char smem_raw[];
    uint32_t sb_raw = smem_u32(smem_raw);
    uint32_t pad = ((sb_raw + 127u) & ~127u) - sb_raw;
    char* smem = smem_raw + pad;
    uint32_t sbase = sb_raw + pad;

    const int tid = threadIdx.x, wid = tid >> 5, lid = tid & 31;
    const int wm = wid >> 2, wn = wid & 3;         // 2 x 4 warp grid, 64x64 tiles
    const float wl2 = (*wp) * 1.44269504089f;      // w * log2(e): exp -> single ex2

    // balanced contiguous unit range for this CTA
    const int s = (blockIdx.x * NUNITS) / GRID_MAIN;
    const int e = ((blockIdx.x + 1) * NUNITS) / GRID_MAIN;
    const int it0 = s >> 5, it1 = (e - 1) >> 5;

    // ldmatrix lane geometry (xor-swizzled 16B chunks within 128B rows)
    const int a_row0 = wm * 64 + (lid & 7) + ((lid >> 3) & 1) * 8;  // + mf*16
    const int a_k = lid >> 4;
    const int a_sw = a_row0 & 7;
    const int b_row0 = wn * 64 + (lid & 7) + ((lid >> 4) & 1) * 8;  // + p*16
    const int b_k = (lid >> 3) & 1;
    const int b_sw = b_row0 & 7;

    float acc[4][8][4];
#pragma unroll
    for (int mf = 0; mf < 4; mf++)
#pragma unroll
        for (int nf = 0; nf < 8; nf++)
#pragma unroll
            for (int k = 0; k < 4; k++) acc[mf][nf][k] = 0.f;

#pragma unroll 1
    for (int it = it0; it <= it1; ++it) {
        const int u_lo = (s > it * 32) ? s : it * 32;
        const int u_hi = (e < (it + 1) * 32) ? e : (it + 1) * 32;
        const int slot = u_lo - it * 32;
        const int nloc = (u_hi - u_lo) * 8;        // chunks this segment (>= 8)

        float rs[8];
#pragma unroll
        for (int r = 0; r < 8; r++) rs[r] = 0.f;

        // ---- segment prologue: group0 = P tile + B chunk 0; group1 = B chunk 1 ----
        {
            const char* psrc = (const char*)(g_P + (size_t)it * TILE_M * DIM);
            for (int i = tid; i < NKC * 1024; i += 256) {
                int blk = i >> 10, v = i & 1023;
                int row = v >> 3, c = v & 7;
                CPA16(sbase + SM_P + blk * PBLK + row * 128 + ((c ^ (row & 7)) << 4),
                      psrc + (size_t)row * (DIM * 2) + blk * 128 + c * 16);
            }
            int jt0 = u_lo & 31;
            issue_bchunk(sbase + SM_AB,
                         (const char*)(g_A + (size_t)jt0 * TILE_N * DIM), tid);
            CPA_COMMIT();
            {   // chunk 1 (nloc >= 8, no guard needed)
                int u = u_lo, jt = u & 31;
                issue_bchunk(sbase + SM_AB + 1 * BBLK,
                             (const char*)(g_A + (size_t)jt * TILE_N * DIM) + 1 * 128,
                             tid);
                CPA_COMMIT();
            }
        }

#pragma unroll 1
        for (int cl = 0; cl < nloc; ++cl) {
            CPA_WAIT1();         // pending <= 1 -> chunk cl (and P on cl==0) resident
            __syncthreads();     // SOLE barrier this chunk

            // issue chunk cl+2 into buf (cl+2)%NBUF == (cl-1)%NBUF.
            // Safe: every warp finished computing chunk cl-1 before this barrier.
            {
                int cn = cl + 2;
                if (cn < nloc) {
                    int u = u_lo + (cn >> 3), jt = u & 31, kc = cn & 7;
                    issue_bchunk(sbase + SM_AB + (cn % NBUF) * BBLK,
                                 (const char*)(g_A + (size_t)jt * TILE_N * DIM) + kc * 128,
                                 tid);
                }
                CPA_COMMIT();    // empty groups keep the count aligned
            }

            // ---- compute chunk cl: 64 k-elems = 4 mma k-steps ----
            const uint32_t pb = sbase + SM_P + (cl & 7) * PBLK;
            const uint32_t bb = sbase + SM_AB + (cl % NBUF) * BBLK;
#pragma unroll
            for (int ks = 0; ks < 4; ++ks) {
                uint32_t a[4][4];
#pragma unroll
                for (int mf = 0; mf < 4; ++mf) {
                    uint32_t addr = pb + (uint32_t)(a_row0 + mf * 16) * 128 +
                                    (uint32_t)(((2 * ks + a_k) ^ a_sw) << 4);
                    LDSM4(a[mf][0], a[mf][1], a[mf][2], a[mf][3], addr);
                }
                uint32_t b[8][2];
#pragma unroll
                for (int p = 0; p < 4; ++p) {
                    uint32_t addr = bb + (uint32_t)(b_row0 + p * 16) * 128 +
                                    (uint32_t)(((2 * ks + b_k) ^ b_sw) << 4);
                    uint32_t r0, r1, r2, r3;
                    LDSM4(r0, r1, r2, r3, addr);
                    b[2 * p][0] = r0; b[2 * p][1] = r1;
                    b[2 * p + 1][0] = r2; b[2 * p + 1][1] = r3;
                }
#pragma unroll
                for (int mf = 0; mf < 4; ++mf)
#pragma unroll
                    for (int nf = 0; nf < 8; ++nf)
                        mma16816(acc[mf][nf], a[mf], b[nf]);
            }

            // ---- per-j-tile epilogue: ex2-accumulate, reset accumulators ----
            if ((cl & 7) == 7) {
#pragma unroll
                for (int mf = 0; mf < 4; ++mf)
#pragma unroll
                    for (int nf = 0; nf < 8; ++nf) {
                        rs[mf * 2 + 0] += ex2f(wl2 * acc[mf][nf][0]) +
                                          ex2f(wl2 * acc[mf][nf][1]);
                        rs[mf * 2 + 1] += ex2f(wl2 * acc[mf][nf][2]) +
                                          ex2f(wl2 * acc[mf][nf][3]);
#pragma unroll
                        for (int k = 0; k < 4; k++) acc[mf][nf][k] = 0.f;
                    }
            }
        }

        // ---- segment drain + flush row-sums to g_partial[it][slot][row] ----
        CPA_WAIT0();
        __syncthreads();         // buffers idle: red overlay at SM_AB is safe
#pragma unroll
        for (int r = 0; r < 8; ++r) {
            rs[r] += __shfl_xor_sync(0xffffffffu, rs[r], 1);
            rs[r] += __shfl_xor_sync(0xffffffffu, rs[r], 2);
        }
        float* red = (float*)(smem + SM_RED);
        if ((lid & 3) == 0) {
            int g = lid >> 2;
#pragma unroll
            for (int mf = 0; mf < 4; ++mf) {
                int rl0 = wm * 64 + mf * 16 + g;
                red[(rl0) * 4 + wn] = rs[mf * 2 + 0];
                red[(rl0 + 8) * 4 + wn] = rs[mf * 2 + 1];
            }
        }
        __syncthreads();
        if (tid < 128) {
            float sm = red[tid * 4 + 0] + red[tid * 4 + 1] +
                       red[tid * 4 + 2] + red[tid * 4 + 3];
            g_partial[(it * 32 + slot) * 128 + tid] = sm;
        }
        __syncthreads();         // red read done before next segment reuses buffers
    }
}

// ---------------- kernel 3: per-row log + block partials + fused finalize ----------------
__global__ void __launch_bounds__(256) lse_kernel(const float* __restrict__ wp,
                                                  float* __restrict__ out) {
    __shared__ float red[256];
    int tid = threadIdx.x;
    int i = blockIdx.x * 256 + tid;       // global row
    int itile = i >> 7, rloc = i & 127;
    float w = *wp;
    float es = 0.f;
#pragma unroll
    for (int sl = 0; sl < 32; ++sl)
        es += g_partial[(itile * 32 + sl) * 128 + rloc];   // unwritten slots are 0
    red[tid] = logf(es) - w * g_diag[i];
    __syncthreads();
    for (int o = 128; o; o >>= 1) {
        if (tid < o) red[tid] += red[tid + o];
        __syncthreads();
    }
    if (tid == 0) {
        g_blk[blockIdx.x] = red[0];
        __threadfence();
        int prev = atomicAdd(&g_ctr, 1);
        if (prev == 31) {                 // last arriving block finalizes
            float s = 0.f;
#pragma unroll
            for (int q = 0; q < 32; ++q) s += g_blk[q];   // fixed order: deterministic
            out[0] = s / (float)NPAIR;
            g_ctr = 0;                    // reset for graph replay
        }
    }
}

// ---------------- launch ----------------
extern "C" void kernel_launch(void* const* d_in, const int* in_sizes, int n_in,
                              void* d_out, int out_size) {
    const float* x = (const float*)d_in[0];
    const float* wp = (const float*)d_in[1];
    // b cancels analytically: lse_i - logit_ii is independent of b.

    cudaFuncSetAttribute(angle_main, cudaFuncAttributeMaxDynamicSharedMemorySize, SM_DYN);

    prep_kernel<<<NPAIR / 8, 256>>>(x);
    angle_main<<<GRID_MAIN, 256, SM_DYN>>>(wp);
    lse_kernel<<<32, 256>>>(wp, (float*)d_out);
}

// round 11
// speedup vs baseline: 1.3273x; 1.0253x over previous
#include <cuda_runtime.h>
#include <cuda_bf16.h>
#include <stdint.h>

// ---------------- problem constants ----------------
#define DIM        512
#define NPAIR      8192
#define TILE_M     128
#define TILE_N     256
#define NUNITS     2048           // 64 i-tiles x 32 j-tiles (128x256 each)
#define GRID_MAIN  148            // one CTA per SM, balanced unit ranges
#define NKC        8              // K chunks of 64 bf16 (128 B per row)
#define PBLK       16384          // P chunk: 128 rows x 128 B
#define BBLK       32768          // B chunk: 256 rows x 128 B
#define NBUF       3              // B-chunk ring depth (issue-ahead-2)

// ---------------- smem layout (offsets from 128-aligned base) ----------------
#define SM_P       0
#define SM_AB      (SM_P + NKC * PBLK)               // 131072
#define SM_RED     SM_AB                             // overlay: used only post-drain
#define SM_DYN     (SM_AB + NBUF * BBLK + 128)       // 229504 <= 232448 cap

// ---------------- device scratch (static: allowed; zero-initialized) ----------------
__device__ __nv_bfloat16 g_P[(size_t)NPAIR * DIM];   // normalized positive rows
__device__ __nv_bfloat16 g_A[(size_t)NPAIR * DIM];   // normalized anchor rows
__device__ float g_partial[64 * 32 * 128];           // [i-tile][slot][row], unwritten=0
__device__ float g_diag[NPAIR];                      // fp32 cos_ii (exact)
__device__ float g_blk[32];                          // lse stage-1 partials
__device__ int   g_ctr;                              // last-block arrival counter

// ---------------- PTX helpers (base-ISA only: no tcgen05 on compute_103) ----------------
static __device__ __forceinline__ uint32_t smem_u32(const void* p) {
    uint32_t a;
    asm("{ .reg .u64 t; cvta.to.shared.u64 t, %1; cvt.u32.u64 %0, t; }"
        : "=r"(a) : "l"(p));
    return a;
}

#define CPA16(dst, src) \
    asm volatile("cp.async.cg.shared.global [%0], [%1], 16;" :: "r"(dst), "l"(src))
#define CPA_COMMIT() asm volatile("cp.async.commit_group;" ::: "memory")
#define CPA_WAIT1()  asm volatile("cp.async.wait_group 1;" ::: "memory")
#define CPA_WAIT0()  asm volatile("cp.async.wait_group 0;" ::: "memory")

#define LDSM4(r0, r1, r2, r3, addr) \
    asm volatile("ldmatrix.sync.aligned.m8n8.x4.shared.b16 {%0,%1,%2,%3}, [%4];" \
                 : "=r"(r0), "=r"(r1), "=r"(r2), "=r"(r3) : "r"(addr))

static __device__ __forceinline__ void mma16816(float* d, const uint32_t* a,
                                                const uint32_t* b) {
    asm volatile(
        "mma.sync.aligned.m16n8k16.row.col.f32.bf16.bf16.f32 "
        "{%0,%1,%2,%3}, {%4,%5,%6,%7}, {%8,%9}, {%0,%1,%2,%3};"
        : "+f"(d[0]), "+f"(d[1]), "+f"(d[2]), "+f"(d[3])
        : "r"(a[0]), "r"(a[1]), "r"(a[2]), "r"(a[3]), "r"(b[0]), "r"(b[1]));
}

static __device__ __forceinline__ float ex2f(float x) {
    float r;
    asm("ex2.approx.ftz.f32 %0, %1;" : "=f"(r) : "f"(x));
    return r;
}

// ---------------- kernel 1: per-pair normalize + bf16 write + exact fp32 diag ----------------
__global__ void __launch_bounds__(256) prep_kernel(const float* __restrict__ x) {
    int pair = blockIdx.x * 8 + (threadIdx.x >> 5);
    int lid = threadIdx.x & 31;
    const float4* ar = (const float4*)(x + (size_t)(2 * pair) * DIM);      // anchor
    const float4* pr = (const float4*)(x + (size_t)(2 * pair + 1) * DIM);  // positive
    float4 va[4], vp[4];
    float ssa = 0.f, ssp = 0.f, dp = 0.f;
#pragma unroll
    for (int i = 0; i < 4; i++) {
        va[i] = ar[lid + i * 32];
        vp[i] = pr[lid + i * 32];
        ssa += va[i].x * va[i].x + va[i].y * va[i].y + va[i].z * va[i].z + va[i].w * va[i].w;
        ssp += vp[i].x * vp[i].x + vp[i].y * vp[i].y + vp[i].z * vp[i].z + vp[i].w * vp[i].w;
        dp  += va[i].x * vp[i].x + va[i].y * vp[i].y + va[i].z * vp[i].z + va[i].w * vp[i].w;
    }
#pragma unroll
    for (int o = 16; o; o >>= 1) {
        ssa += __shfl_xor_sync(0xffffffffu, ssa, o);
        ssp += __shfl_xor_sync(0xffffffffu, ssp, o);
        dp  += __shfl_xor_sync(0xffffffffu, dp, o);
    }
    float inva = rsqrtf(ssa);   // norms ~sqrt(512): EPS clamp never binds
    float invp = rsqrtf(ssp);
    if (lid == 0) g_diag[pair] = dp * inva * invp;   // exact fp32 diagonal

    __nv_bfloat16* da = g_A + (size_t)pair * DIM;
    __nv_bfloat16* dq = g_P + (size_t)pair * DIM;
#pragma unroll
    for (int i = 0; i < 4; i++) {
        __nv_bfloat162 l0 = __floats2bfloat162_rn(va[i].x * inva, va[i].y * inva);
        __nv_bfloat162 h0 = __floats2bfloat162_rn(va[i].z * inva, va[i].w * inva);
        uint2 pa; pa.x = *(uint32_t*)&l0; pa.y = *(uint32_t*)&h0;
        *(uint2*)(da + (size_t)(lid + i * 32) * 4) = pa;
        __nv_bfloat162 l1 = __floats2bfloat162_rn(vp[i].x * invp, vp[i].y * invp);
        __nv_bfloat162 h1 = __floats2bfloat162_rn(vp[i].z * invp, vp[i].w * invp);
        uint2 pp; pp.x = *(uint32_t*)&l1; pp.y = *(uint32_t*)&h1;
        *(uint2*)(dq + (size_t)(lid + i * 32) * 4) = pp;
    }
}

// issue one B chunk (256 rows x 128 B, swizzled) via cp.async
static __device__ __forceinline__ void issue_bchunk(uint32_t dst, const char* src,
                                                    int tid) {
    for (int u = tid; u < 2048; u += 256) {
        int row = u >> 3, cc = u & 7;
        CPA16(dst + row * 128 + ((cc ^ (row & 7)) << 4),
              src + (size_t)row * (DIM * 2) + cc * 16);
    }
}

// ---------------- kernel 2: balanced fused cos-GEMM + exp row-sums ----------------
__global__ void __launch_bounds__(256, 1) angle_main(const float* __restrict__ wp) {
    extern __shared__ char smem_raw[];
    uint32_t sb_raw = smem_u32(smem_raw);
    uint32_t pad = ((sb_raw + 127u) & ~127u) - sb_raw;
    char* smem = smem_raw + pad;
    uint32_t sbase = sb_raw + pad;

    const int tid = threadIdx.x, wid = tid >> 5, lid = tid & 31;
    const int wm = wid >> 2, wn = wid & 3;         // 2 x 4 warp grid, 64x64 tiles
    const float wl2 = (*wp) * 1.44269504089f;      // w * log2(e): exp -> single ex2

    // balanced contiguous unit range for this CTA
    const int s = (blockIdx.x * NUNITS) / GRID_MAIN;
    const int e = ((blockIdx.x + 1) * NUNITS) / GRID_MAIN;
    const int it0 = s >> 5, it1 = (e - 1) >> 5;

    // ldmatrix lane geometry (xor-swizzled 16B chunks within 128B rows)
    const int a_row0 = wm * 64 + (lid & 7) + ((lid >> 3) & 1) * 8;  // + mf*16
    const int a_k = lid >> 4;
    const int a_sw = a_row0 & 7;
    const int b_row0 = wn * 64 + (lid & 7) + ((lid >> 4) & 1) * 8;  // + p*16
    const int b_k = (lid >> 3) & 1;
    const int b_sw = b_row0 & 7;

    float acc[4][8][4];
#pragma unroll
    for (int mf = 0; mf < 4; mf++)
#pragma unroll
        for (int nf = 0; nf < 8; nf++)
#pragma unroll
            for (int k = 0; k < 4; k++) acc[mf][nf][k] = 0.f;

#pragma unroll 1
    for (int it = it0; it <= it1; ++it) {
        const int u_lo = (s > it * 32) ? s : it * 32;
        const int u_hi = (e < (it + 1) * 32) ? e : (it + 1) * 32;
        const int slot = u_lo - it * 32;
        const int nloc = (u_hi - u_lo) * 8;        // chunks this segment (>= 8)

        float rs[8];
#pragma unroll
        for (int r = 0; r < 8; r++) rs[r] = 0.f;

        // ---- segment prologue: group0 = P tile + B chunk 0; group1 = B chunk 1 ----
        {
            const char* psrc = (const char*)(g_P + (size_t)it * TILE_M * DIM);
            for (int i = tid; i < NKC * 1024; i += 256) {
                int blk = i >> 10, v = i & 1023;
                int row = v >> 3, c = v & 7;
                CPA16(sbase + SM_P + blk * PBLK + row * 128 + ((c ^ (row & 7)) << 4),
                      psrc + (size_t)row * (DIM * 2) + blk * 128 + c * 16);
            }
            int jt0 = u_lo & 31;
            issue_bchunk(sbase + SM_AB,
                         (const char*)(g_A + (size_t)jt0 * TILE_N * DIM), tid);
            CPA_COMMIT();
            {   // chunk 1 (nloc >= 8, no guard needed)
                int u = u_lo, jt = u & 31;
                issue_bchunk(sbase + SM_AB + 1 * BBLK,
                             (const char*)(g_A + (size_t)jt * TILE_N * DIM) + 1 * 128,
                             tid);
                CPA_COMMIT();
            }
        }

#pragma unroll 1
        for (int cl = 0; cl < nloc; ++cl) {
            CPA_WAIT1();         // pending <= 1 -> chunk cl (and P on cl==0) resident
            __syncthreads();     // SOLE barrier this chunk

            const uint32_t pb = sbase + SM_P + (cl & 7) * PBLK;
            const uint32_t bb = sbase + SM_AB + (cl % NBUF) * BBLK;

            // ---- software-pipelined fragments: load ks+1 while mma consumes ks ----
            uint32_t af[2][4][4], bf[2][8][2];
#pragma unroll
            for (int mf = 0; mf < 4; ++mf) {
                uint32_t addr = pb + (uint32_t)(a_row0 + mf * 16) * 128 +
                                (uint32_t)((a_k ^ a_sw) << 4);
                LDSM4(af[0][mf][0], af[0][mf][1], af[0][mf][2], af[0][mf][3], addr);
            }
#pragma unroll
            for (int p = 0; p < 4; ++p) {
                uint32_t addr = bb + (uint32_t)(b_row0 + p * 16) * 128 +
                                (uint32_t)((b_k ^ b_sw) << 4);
                uint32_t r0, r1, r2, r3;
                LDSM4(r0, r1, r2, r3, addr);
                bf[0][2 * p][0] = r0; bf[0][2 * p][1] = r1;
                bf[0][2 * p + 1][0] = r2; bf[0][2 * p + 1][1] = r3;
            }

            // prefetch chunk cl+2 AFTER the critical-path frag loads (2 chunks of slack)
            {
                int cn = cl + 2;
                if (cn < nloc) {
                    int u = u_lo + (cn >> 3), jt = u & 31, kc = cn & 7;
                    issue_bchunk(sbase + SM_AB + (cn % NBUF) * BBLK,
                                 (const char*)(g_A + (size_t)jt * TILE_N * DIM) + kc * 128,
                                 tid);
                }
                CPA_COMMIT();    // empty groups keep the count aligned
            }

#pragma unroll
            for (int ks = 0; ks < 4; ++ks) {
                const int cur = ks & 1, nxt = cur ^ 1;
                if (ks < 3) {    // issue next k-step's LDSM ahead of this mma block
#pragma unroll
                    for (int mf = 0; mf < 4; ++mf) {
                        uint32_t addr = pb + (uint32_t)(a_row0 + mf * 16) * 128 +
                                        (uint32_t)(((2 * (ks + 1) + a_k) ^ a_sw) << 4);
                        LDSM4(af[nxt][mf][0], af[nxt][mf][1],
                              af[nxt][mf][2], af[nxt][mf][3], addr);
                    }
#pragma unroll
                    for (int p = 0; p < 4; ++p) {
                        uint32_t addr = bb + (uint32_t)(b_row0 + p * 16) * 128 +
                                        (uint32_t)(((2 * (ks + 1) + b_k) ^ b_sw) << 4);
                        uint32_t r0, r1, r2, r3;
                        LDSM4(r0, r1, r2, r3, addr);
                        bf[nxt][2 * p][0] = r0; bf[nxt][2 * p][1] = r1;
                        bf[nxt][2 * p + 1][0] = r2; bf[nxt][2 * p + 1][1] = r3;
                    }
                }
#pragma unroll
                for (int mf = 0; mf < 4; ++mf)
#pragma unroll
                    for (int nf = 0; nf < 8; ++nf)
                        mma16816(acc[mf][nf], af[cur][mf], bf[cur][nf]);
            }

            // ---- per-j-tile epilogue: ex2-accumulate, reset accumulators ----
            if ((cl & 7) == 7) {
#pragma unroll
                for (int mf = 0; mf < 4; ++mf)
#pragma unroll
                    for (int nf = 0; nf < 8; ++nf) {
                        rs[mf * 2 + 0] += ex2f(wl2 * acc[mf][nf][0]) +
                                          ex2f(wl2 * acc[mf][nf][1]);
                        rs[mf * 2 + 1] += ex2f(wl2 * acc[mf][nf][2]) +
                                          ex2f(wl2 * acc[mf][nf][3]);
#pragma unroll
                        for (int k = 0; k < 4; k++) acc[mf][nf][k] = 0.f;
                    }
            }
        }

        // ---- segment drain + flush row-sums to g_partial[it][slot][row] ----
        CPA_WAIT0();
        __syncthreads();         // buffers idle: red overlay at SM_AB is safe
#pragma unroll
        for (int r = 0; r < 8; ++r) {
            rs[r] += __shfl_xor_sync(0xffffffffu, rs[r], 1);
            rs[r] += __shfl_xor_sync(0xffffffffu, rs[r], 2);
        }
        float* red = (float*)(smem + SM_RED);
        if ((lid & 3) == 0) {
            int g = lid >> 2;
#pragma unroll
            for (int mf = 0; mf < 4; ++mf) {
                int rl0 = wm * 64 + mf * 16 + g;
                red[(rl0) * 4 + wn] = rs[mf * 2 + 0];
                red[(rl0 + 8) * 4 + wn] = rs[mf * 2 + 1];
            }
        }
        __syncthreads();
        if (tid < 128) {
            float sm = red[tid * 4 + 0] + red[tid * 4 + 1] +
                       red[tid * 4 + 2] + red[tid * 4 + 3];
            g_partial[(it * 32 + slot) * 128 + tid] = sm;
        }
        __syncthreads();         // red read done before next segment reuses buffers
    }
}

// ---------------- kernel 3: per-row log + block partials + fused finalize ----------------
__global__ void __launch_bounds__(256) lse_kernel(const float* __restrict__ wp,
                                                  float* __restrict__ out) {
    __shared__ float red[256];
    int tid = threadIdx.x;
    int i = blockIdx.x * 256 + tid;       // global row
    int itile = i >> 7, rloc = i & 127;
    float w = *wp;
    float es = 0.f;
#pragma unroll
    for (int sl = 0; sl < 32; ++sl)
        es += g_partial[(itile * 32 + sl) * 128 + rloc];   // unwritten slots are 0
    red[tid] = logf(es) - w * g_diag[i];
    __syncthreads();
    for (int o = 128; o; o >>= 1) {
        if (tid < o) red[tid] += red[tid + o];
        __syncthreads();
    }
    if (tid == 0) {
        g_blk[blockIdx.x] = red[0];
        __threadfence();
        int prev = atomicAdd(&g_ctr, 1);
        if (prev == 31) {                 // last arriving block finalizes
            float s = 0.f;
#pragma unroll
            for (int q = 0; q < 32; ++q) s += g_blk[q];   // fixed order: deterministic
            out[0] = s / (float)NPAIR;
            g_ctr = 0;                    // reset for graph replay
        }
    }
}

// ---------------- launch ----------------
extern "C" void kernel_launch(void* const* d_in, const int* in_sizes, int n_in,
                              void* d_out, int out_size) {
    const float* x = (const float*)d_in[0];
    const float* wp = (const float*)d_in[1];
    // b cancels analytically: lse_i - logit_ii is independent of b.

    cudaFuncSetAttribute(angle_main, cudaFuncAttributeMaxDynamicSharedMemorySize, SM_DYN);

    prep_kernel<<<NPAIR / 8, 256>>>(x);
    angle_main<<<GRID_MAIN, 256, SM_DYN>>>(wp);
    lse_kernel<<<32, 256>>>(wp, (float*)d_out);
}

// round 12
// speedup vs baseline: 1.3807x; 1.0402x over previous
#include <cuda_runtime.h>
#include <cuda_bf16.h>
#include <stdint.h>

// ---------------- problem constants ----------------
#define DIM        512
#define NPAIR      8192
#define TILE_M     128
#define TILE_N     256
#define NUNITS     2048           // 64 i-tiles x 32 j-tiles (128x256 each)
#define GRID_MAIN  148            // one CTA per SM, balanced unit ranges (one wave)
#define NKC        8              // K chunks of 64 bf16 (128 B per row)
#define PBLK       16384          // P chunk: 128 rows x 128 B
#define BBLK       32768          // B chunk: 256 rows x 128 B
#define NBUF       3              // B-chunk ring depth (issue-ahead-2)

// ---------------- smem layout (offsets from 128-aligned base) ----------------
#define SM_P       0
#define SM_AB      (SM_P + NKC * PBLK)               // 131072
#define SM_RED     SM_AB                             // overlay: used only post-drain
#define SM_DYN     (SM_AB + NBUF * BBLK + 128)       // 229504 <= 232448 cap

// ---------------- device scratch (static: allowed; zero-initialized) ----------------
__device__ __nv_bfloat16 g_P[(size_t)NPAIR * DIM];   // normalized positive rows
__device__ __nv_bfloat16 g_A[(size_t)NPAIR * DIM];   // normalized anchor rows
__device__ float g_partial[64 * 32 * 128];           // [i-tile][slot][row], unwritten=0
__device__ float g_diag[NPAIR];                      // fp32 cos_ii (exact)
__device__ float g_blk[32];                          // lse block partials
__device__ unsigned g_ctr;                           // CTA arrival counter
__device__ unsigned g_ctr2;                          // lse-block completion counter

// ---------------- PTX helpers (base-ISA only: no tcgen05 on compute_103) ----------------
static __device__ __forceinline__ uint32_t smem_u32(const void* p) {
    uint32_t a;
    asm("{ .reg .u64 t; cvta.to.shared.u64 t, %1; cvt.u32.u64 %0, t; }"
        : "=r"(a) : "l"(p));
    return a;
}

#define CPA16(dst, src) \
    asm volatile("cp.async.cg.shared.global [%0], [%1], 16;" :: "r"(dst), "l"(src))
#define CPA_COMMIT() asm volatile("cp.async.commit_group;" ::: "memory")
#define CPA_WAIT1()  asm volatile("cp.async.wait_group 1;" ::: "memory")
#define CPA_WAIT0()  asm volatile("cp.async.wait_group 0;" ::: "memory")

#define LDSM4(r0, r1, r2, r3, addr) \
    asm volatile("ldmatrix.sync.aligned.m8n8.x4.shared.b16 {%0,%1,%2,%3}, [%4];" \
                 : "=r"(r0), "=r"(r1), "=r"(r2), "=r"(r3) : "r"(addr))

static __device__ __forceinline__ void mma16816(float* d, const uint32_t* a,
                                                const uint32_t* b) {
    asm volatile(
        "mma.sync.aligned.m16n8k16.row.col.f32.bf16.bf16.f32 "
        "{%0,%1,%2,%3}, {%4,%5,%6,%7}, {%8,%9}, {%0,%1,%2,%3};"
        : "+f"(d[0]), "+f"(d[1]), "+f"(d[2]), "+f"(d[3])
        : "r"(a[0]), "r"(a[1]), "r"(a[2]), "r"(a[3]), "r"(b[0]), "r"(b[1]));
}

static __device__ __forceinline__ float ex2f(float x) {
    float r;
    asm("ex2.approx.ftz.f32 %0, %1;" : "=f"(r) : "f"(x));
    return r;
}

// ---------------- kernel 1: per-pair normalize + bf16 write + exact fp32 diag ----------------
__global__ void __launch_bounds__(256) prep_kernel(const float* __restrict__ x) {
    int pair = blockIdx.x * 8 + (threadIdx.x >> 5);
    int lid = threadIdx.x & 31;
    const float4* ar = (const float4*)(x + (size_t)(2 * pair) * DIM);      // anchor
    const float4* pr = (const float4*)(x + (size_t)(2 * pair + 1) * DIM);  // positive
    float4 va[4], vp[4];
    float ssa = 0.f, ssp = 0.f, dp = 0.f;
#pragma unroll
    for (int i = 0; i < 4; i++) {
        va[i] = ar[lid + i * 32];
        vp[i] = pr[lid + i * 32];
        ssa += va[i].x * va[i].x + va[i].y * va[i].y + va[i].z * va[i].z + va[i].w * va[i].w;
        ssp += vp[i].x * vp[i].x + vp[i].y * vp[i].y + vp[i].z * vp[i].z + vp[i].w * vp[i].w;
        dp  += va[i].x * vp[i].x + va[i].y * vp[i].y + va[i].z * vp[i].z + va[i].w * vp[i].w;
    }
#pragma unroll
    for (int o = 16; o; o >>= 1) {
        ssa += __shfl_xor_sync(0xffffffffu, ssa, o);
        ssp += __shfl_xor_sync(0xffffffffu, ssp, o);
        dp  += __shfl_xor_sync(0xffffffffu, dp, o);
    }
    float inva = rsqrtf(ssa);   // norms ~sqrt(512): EPS clamp never binds
    float invp = rsqrtf(ssp);
    if (lid == 0) g_diag[pair] = dp * inva * invp;   // exact fp32 diagonal

    __nv_bfloat16* da = g_A + (size_t)pair * DIM;
    __nv_bfloat16* dq = g_P + (size_t)pair * DIM;
#pragma unroll
    for (int i = 0; i < 4; i++) {
        __nv_bfloat162 l0 = __floats2bfloat162_rn(va[i].x * inva, va[i].y * inva);
        __nv_bfloat162 h0 = __floats2bfloat162_rn(va[i].z * inva, va[i].w * inva);
        uint2 pa; pa.x = *(uint32_t*)&l0; pa.y = *(uint32_t*)&h0;
        *(uint2*)(da + (size_t)(lid + i * 32) * 4) = pa;
        __nv_bfloat162 l1 = __floats2bfloat162_rn(vp[i].x * invp, vp[i].y * invp);
        __nv_bfloat162 h1 = __floats2bfloat162_rn(vp[i].z * invp, vp[i].w * invp);
        uint2 pp; pp.x = *(uint32_t*)&l1; pp.y = *(uint32_t*)&h1;
        *(uint2*)(dq + (size_t)(lid + i * 32) * 4) = pp;
    }
}

// issue one B chunk (256 rows x 128 B, swizzled). Per-thread offsets are linear
// in the iteration index: cc = tid&7 and row&7 are invariant (row += 32 per step).
static __device__ __forceinline__ void issue_bchunk(uint32_t dst, const char* src,
                                                    uint32_t d0, uint32_t s0) {
#pragma unroll
    for (int i = 0; i < 8; ++i)
        CPA16(dst + d0 + (uint32_t)i * 4096u, src + s0 + (size_t)i * 32768u);
}

// ---------------- kernel 2: balanced fused cos-GEMM + exp row-sums + fused lse tail ----------------
__global__ void __launch_bounds__(256, 1) angle_main(const float* __restrict__ wp,
                                                     float* __restrict__ out) {
    extern __shared__ char smem_raw[];
    uint32_t sb_raw = smem_u32(smem_raw);
    uint32_t pad = ((sb_raw + 127u) & ~127u) - sb_raw;
    char* smem = smem_raw + pad;
    uint32_t sbase = sb_raw + pad;

    const int tid = threadIdx.x, wid = tid >> 5, lid = tid & 31;
    const int wm = wid >> 2, wn = wid & 3;         // 2 x 4 warp grid, 64x64 tiles
    const float w = *wp;
    const float wl2 = w * 1.44269504089f;          // w * log2(e): exp -> single ex2

    // per-thread cp.async base offsets (linear stepping inside issue_bchunk)
    const uint32_t cpa_d0 = (uint32_t)((tid >> 3) * 128 +
                            ((((tid & 7) ^ ((tid >> 3) & 7))) << 4));
    const uint32_t cpa_s0 = (uint32_t)((tid >> 3) * 1024 + (tid & 7) * 16);

    // balanced contiguous unit range for this CTA
    const int s = (blockIdx.x * NUNITS) / GRID_MAIN;
    const int e = ((blockIdx.x + 1) * NUNITS) / GRID_MAIN;
    const int it0 = s >> 5, it1 = (e - 1) >> 5;

    // ldmatrix lane geometry (xor-swizzled 16B chunks within 128B rows)
    const int a_row0 = wm * 64 + (lid & 7) + ((lid >> 3) & 1) * 8;  // + mf*16
    const int a_k = lid >> 4;
    const int a_sw = a_row0 & 7;
    const int b_row0 = wn * 64 + (lid & 7) + ((lid >> 4) & 1) * 8;  // + p*16
    const int b_k = (lid >> 3) & 1;
    const int b_sw = b_row0 & 7;

    float acc[4][8][4];
#pragma unroll
    for (int mf = 0; mf < 4; mf++)
#pragma unroll
        for (int nf = 0; nf < 8; nf++)
#pragma unroll
            for (int k = 0; k < 4; k++) acc[mf][nf][k] = 0.f;

#pragma unroll 1
    for (int it = it0; it <= it1; ++it) {
        const int u_lo = (s > it * 32) ? s : it * 32;
        const int u_hi = (e < (it + 1) * 32) ? e : (it + 1) * 32;
        const int slot = u_lo - it * 32;
        const int nloc = (u_hi - u_lo) * 8;        // chunks this segment (>= 8)

        float rs[8];
#pragma unroll
        for (int r = 0; r < 8; r++) rs[r] = 0.f;

        // ---- segment prologue: group0 = P tile + B chunk 0; group1 = B chunk 1 ----
        {
            const char* psrc = (const char*)(g_P + (size_t)it * TILE_M * DIM);
            for (int i = tid; i < NKC * 1024; i += 256) {
                int blk = i >> 10, v = i & 1023;
                int row = v >> 3, c = v & 7;
                CPA16(sbase + SM_P + blk * PBLK + row * 128 + ((c ^ (row & 7)) << 4),
                      psrc + (size_t)row * (DIM * 2) + blk * 128 + c * 16);
            }
            int jt0 = u_lo & 31;
            issue_bchunk(sbase + SM_AB,
                         (const char*)(g_A + (size_t)jt0 * TILE_N * DIM),
                         cpa_d0, cpa_s0);
            CPA_COMMIT();
            issue_bchunk(sbase + SM_AB + 1 * BBLK,
                         (const char*)(g_A + (size_t)(u_lo & 31) * TILE_N * DIM) + 128,
                         cpa_d0, cpa_s0);
            CPA_COMMIT();
        }

#pragma unroll 1
        for (int cl = 0; cl < nloc; ++cl) {
            CPA_WAIT1();         // pending <= 1 -> chunk cl (and P on cl==0) resident
            __syncthreads();     // SOLE barrier this chunk

            const uint32_t pb = sbase + SM_P + (cl & 7) * PBLK;
            const uint32_t bb = sbase + SM_AB + (cl % NBUF) * BBLK;

            // ---- software-pipelined fragments: load ks+1 while mma consumes ks ----
            uint32_t af[2][4][4], bf[2][8][2];
#pragma unroll
            for (int mf = 0; mf < 4; ++mf) {
                uint32_t addr = pb + (uint32_t)(a_row0 + mf * 16) * 128 +
                                (uint32_t)((a_k ^ a_sw) << 4);
                LDSM4(af[0][mf][0], af[0][mf][1], af[0][mf][2], af[0][mf][3], addr);
            }
#pragma unroll
            for (int p = 0; p < 4; ++p) {
                uint32_t addr = bb + (uint32_t)(b_row0 + p * 16) * 128 +
                                (uint32_t)((b_k ^ b_sw) << 4);
                uint32_t r0, r1, r2, r3;
                LDSM4(r0, r1, r2, r3, addr);
                bf[0][2 * p][0] = r0; bf[0][2 * p][1] = r1;
                bf[0][2 * p + 1][0] = r2; bf[0][2 * p + 1][1] = r3;
            }

            // prefetch chunk cl+2 AFTER the critical-path frag loads (2 chunks of slack)
            {
                int cn = cl + 2;
                if (cn < nloc) {
                    int u = u_lo + (cn >> 3), jt = u & 31, kc = cn & 7;
                    issue_bchunk(sbase + SM_AB + (cn % NBUF) * BBLK,
                                 (const char*)(g_A + (size_t)jt * TILE_N * DIM) + kc * 128,
                                 cpa_d0, cpa_s0);
                }
                CPA_COMMIT();    // empty groups keep the count aligned
            }

#pragma unroll
            for (int ks = 0; ks < 4; ++ks) {
                const int cur = ks & 1, nxt = cur ^ 1;
                if (ks < 3) {    // issue next k-step's LDSM ahead of this mma block
#pragma unroll
                    for (int mf = 0; mf < 4; ++mf) {
                        uint32_t addr = pb + (uint32_t)(a_row0 + mf * 16) * 128 +
                                        (uint32_t)(((2 * (ks + 1) + a_k) ^ a_sw) << 4);
                        LDSM4(af[nxt][mf][0], af[nxt][mf][1],
                              af[nxt][mf][2], af[nxt][mf][3], addr);
                    }
#pragma unroll
                    for (int p = 0; p < 4; ++p) {
                        uint32_t addr = bb + (uint32_t)(b_row0 + p * 16) * 128 +
                                        (uint32_t)(((2 * (ks + 1) + b_k) ^ b_sw) << 4);
                        uint32_t r0, r1, r2, r3;
                        LDSM4(r0, r1, r2, r3, addr);
                        bf[nxt][2 * p][0] = r0; bf[nxt][2 * p][1] = r1;
                        bf[nxt][2 * p + 1][0] = r2; bf[nxt][2 * p + 1][1] = r3;
                    }
                }
#pragma unroll
                for (int mf = 0; mf < 4; ++mf)
#pragma unroll
                    for (int nf = 0; nf < 8; ++nf)
                        mma16816(acc[mf][nf], af[cur][mf], bf[cur][nf]);
            }

            // ---- per-j-tile epilogue: ex2-accumulate, reset accumulators ----
            if ((cl & 7) == 7) {
#pragma unroll
                for (int mf = 0; mf < 4; ++mf)
#pragma unroll
                    for (int nf = 0; nf < 8; ++nf) {
                        rs[mf * 2 + 0] += ex2f(wl2 * acc[mf][nf][0]) +
                                          ex2f(wl2 * acc[mf][nf][1]);
                        rs[mf * 2 + 1] += ex2f(wl2 * acc[mf][nf][2]) +
                                          ex2f(wl2 * acc[mf][nf][3]);
#pragma unroll
                        for (int k = 0; k < 4; k++) acc[mf][nf][k] = 0.f;
                    }
            }
        }

        // ---- segment drain + flush row-sums to g_partial[it][slot][row] ----
        CPA_WAIT0();
        __syncthreads();         // buffers idle: red overlay at SM_AB is safe
#pragma unroll
        for (int r = 0; r < 8; ++r) {
            rs[r] += __shfl_xor_sync(0xffffffffu, rs[r], 1);
            rs[r] += __shfl_xor_sync(0xffffffffu, rs[r], 2);
        }
        float* red = (float*)(smem + SM_RED);
        if ((lid & 3) == 0) {
            int g = lid >> 2;
#pragma unroll
            for (int mf = 0; mf < 4; ++mf) {
                int rl0 = wm * 64 + mf * 16 + g;
                red[(rl0) * 4 + wn] = rs[mf * 2 + 0];
                red[(rl0 + 8) * 4 + wn] = rs[mf * 2 + 1];
            }
        }
        __syncthreads();
        if (tid < 128) {
            float sm = red[tid * 4 + 0] + red[tid * 4 + 1] +
                       red[tid * 4 + 2] + red[tid * 4 + 3];
            g_partial[(it * 32 + slot) * 128 + tid] = sm;
        }
        __syncthreads();         // red read done before next segment reuses buffers
    }

    // ================= fused LSE tail =================
    // First 32 arriving CTAs (idle otherwise while stragglers finish) each compute
    // one 256-row lse block once ALL 148 CTAs have published their partials.
    __threadfence();             // publish g_partial before taking a ticket
    volatile unsigned* com = (volatile unsigned*)(smem + SM_RED);
    if (tid == 0) com[0] = atomicAdd(&g_ctr, 1u);
    __syncthreads();
    unsigned arr = com[0];
    if (arr >= 32) return;       // GEMM-only CTA: done

    if (tid == 0) {              // wait for all 148 publications
        while (atomicAdd(&g_ctr, 0u) < (unsigned)GRID_MAIN) __nanosleep(128);
    }
    __syncthreads();
    __threadfence();

    int i = (int)arr * 256 + tid;             // global row
    int itile = i >> 7, rloc = i & 127;
    float es = 0.f;
#pragma unroll
    for (int sl = 0; sl < 32; ++sl)           // __ldcg: bypass (possibly stale) L1
        es += __ldcg(&g_partial[(itile * 32 + sl) * 128 + rloc]);
    float val = logf(es) - w * g_diag[i];

    float* red = (float*)(smem + SM_RED + 64);   // clear of the com slot
    red[tid] = val;
    __syncthreads();
    for (int o = 128; o; o >>= 1) {
        if (tid < o) red[tid] += red[tid + o];
        __syncthreads();
    }
    if (tid == 0) {
        g_blk[arr] = red[0];
        __threadfence();
        unsigned p = atomicAdd(&g_ctr2, 1u);
        if (p == 31u) {                        // last lse block finalizes
            float sfin = 0.f;
#pragma unroll
            for (int q = 0; q < 32; ++q) sfin += __ldcg(&g_blk[q]);  // fixed order
            out[0] = sfin / (float)NPAIR;
            g_ctr = 0u;                        // reset for graph replay
            g_ctr2 = 0u;
        }
    }
}

// ---------------- launch ----------------
extern "C" void kernel_launch(void* const* d_in, const int* in_sizes, int n_in,
                              void* d_out, int out_size) {
    const float* x = (const float*)d_in[0];
    const float* wp = (const float*)d_in[1];
    // b cancels analytically: lse_i - logit_ii is independent of b.

    cudaFuncSetAttribute(angle_main, cudaFuncAttributeMaxDynamicSharedMemorySize, SM_DYN);

    prep_kernel<<<NPAIR / 8, 256>>>(x);
    angle_main<<<GRID_MAIN, 256, SM_DYN>>>(wp, (float*)d_out);
}